// round 3
// baseline (speedup 1.0000x reference)
#include <cuda_runtime.h>
#include <cstdint>

#define N_VARS   2048
#define N_LAYERS 8
#define NODES    4096
#define FAN_IN   4
#define BATCH    8192
#define BT       4              // batch elements per CTA (float4 vector)
#define THREADS  512
#define NODES_PER_THREAD (NODES / THREADS)   // 8

// Packed per-layer child indices (values < 4096 fit in uint16).
__device__ ushort4 g_idx16[N_LAYERS * NODES];

__global__ void prep_idx_kernel(const int* __restrict__ child_idx) {
    int i = blockIdx.x * blockDim.x + threadIdx.x;
    if (i < N_LAYERS * NODES) {
        const int4 p = reinterpret_cast<const int4*>(child_idx)[i];
        ushort4 v;
        v.x = (unsigned short)(p.x & (NODES - 1));
        v.y = (unsigned short)(p.y & (NODES - 1));
        v.z = (unsigned short)(p.z & (NODES - 1));
        v.w = (unsigned short)(p.w & (NODES - 1));
        g_idx16[i] = v;
    }
}

extern __shared__ float4 s_buf[];   // [2 * NODES] float4 = 128 KB

__global__ __launch_bounds__(THREADS, 1)
void spn_kernel(const float* __restrict__ x,
                const unsigned char* __restrict__ marg,
                float* __restrict__ out) {
    float4* buf0 = s_buf;
    float4* buf1 = s_buf + NODES;

    const int tid = threadIdx.x;
    const int b0  = blockIdx.x * BT;

    // -------- Build leaves: buf0[j] = x[:, j], buf0[j+2048] = 1 - x[:, j] --------
    for (int j = tid; j < N_VARS; j += THREADS) {
        const bool m = (marg[j] != 0);
        float4 v;
        v.x = x[(size_t)(b0 + 0) * N_VARS + j];
        v.y = x[(size_t)(b0 + 1) * N_VARS + j];
        v.z = x[(size_t)(b0 + 2) * N_VARS + j];
        v.w = x[(size_t)(b0 + 3) * N_VARS + j];
        float4 w1, w2;
        if (m) {
            w1 = make_float4(1.f, 1.f, 1.f, 1.f);
            w2 = make_float4(1.f, 1.f, 1.f, 1.f);
        } else {
            w1 = v;
            w2 = make_float4(1.f - v.x, 1.f - v.y, 1.f - v.z, 1.f - v.w);
        }
        buf0[j]          = w1;
        buf0[j + N_VARS] = w2;
    }
    __syncthreads();

    float4* cur = buf0;
    float4* nxt = buf1;
    float4  acc = make_float4(0.f, 0.f, 0.f, 0.f);

    #pragma unroll
    for (int l = 0; l < N_LAYERS; l++) {
        const ushort4* __restrict__ idxL = g_idx16 + l * NODES;
        #pragma unroll
        for (int i = 0; i < NODES_PER_THREAD; i++) {
            const int node = tid + i * THREADS;
            const ushort4 c = idxL[node];
            const float4 a = cur[c.x];
            const float4 b = cur[c.y];
            const float4 d = cur[c.z];
            const float4 e = cur[c.w];
            float4 r;
            if ((l & 1) == 0) {   // product layer
                r.x = a.x * b.x * d.x * e.x;
                r.y = a.y * b.y * d.y * e.y;
                r.z = a.z * b.z * d.z * e.z;
                r.w = a.w * b.w * d.w * e.w;
            } else {              // sum layer
                r.x = a.x + b.x + d.x + e.x;
                r.y = a.y + b.y + d.y + e.y;
                r.z = a.z + b.z + d.z + e.z;
                r.w = a.w + b.w + d.w + e.w;
            }
            if (l == N_LAYERS - 1) {
                // Fuse final node-sum: layer 7 is a sum layer, never stored.
                acc.x += r.x; acc.y += r.y; acc.z += r.z; acc.w += r.w;
            } else {
                nxt[node] = r;
            }
        }
        __syncthreads();
        float4* t = cur; cur = nxt; nxt = t;
    }

    // -------- Block reduction of acc (float4) over 512 threads --------
    #pragma unroll
    for (int off = 16; off > 0; off >>= 1) {
        acc.x += __shfl_down_sync(0xffffffffu, acc.x, off);
        acc.y += __shfl_down_sync(0xffffffffu, acc.y, off);
        acc.z += __shfl_down_sync(0xffffffffu, acc.z, off);
        acc.w += __shfl_down_sync(0xffffffffu, acc.w, off);
    }

    __shared__ float4 warp_sums[THREADS / 32];
    const int wid  = tid >> 5;
    const int lane = tid & 31;
    if (lane == 0) warp_sums[wid] = acc;
    __syncthreads();

    if (wid == 0) {
        float4 s = (lane < THREADS / 32) ? warp_sums[lane]
                                         : make_float4(0.f, 0.f, 0.f, 0.f);
        #pragma unroll
        for (int off = 8; off > 0; off >>= 1) {
            s.x += __shfl_down_sync(0xffffffffu, s.x, off);
            s.y += __shfl_down_sync(0xffffffffu, s.y, off);
            s.z += __shfl_down_sync(0xffffffffu, s.z, off);
            s.w += __shfl_down_sync(0xffffffffu, s.w, off);
        }
        if (lane == 0) {
            *reinterpret_cast<float4*>(out + b0) = s;
        }
    }
}

extern "C" void kernel_launch(void* const* d_in, const int* in_sizes, int n_in,
                              void* d_out, int out_size) {
    const float*         x    = (const float*)d_in[0];
    const unsigned char* marg = (const unsigned char*)d_in[1];
    const int*           cidx = (const int*)d_in[2];   // int64 in reference -> int32 in harness
    float*               out  = (float*)d_out;

    // Allow 128 KB dynamic shared memory (idempotent; not a stream op).
    cudaFuncSetAttribute(spn_kernel,
                         cudaFuncAttributeMaxDynamicSharedMemorySize,
                         2 * NODES * (int)sizeof(float4));

    // 1) Pack int32 indices -> ushort4 (deterministic, re-run every launch).
    {
        const int total = N_LAYERS * NODES;
        const int tpb = 256;
        prep_idx_kernel<<<(total + tpb - 1) / tpb, tpb>>>(cidx);
    }

    // 2) Main fused kernel: one CTA per 4 batch rows.
    spn_kernel<<<BATCH / BT, THREADS, 2 * NODES * (int)sizeof(float4)>>>(x, marg, out);
}

// round 6
// speedup vs baseline: 1.0052x; 1.0052x over previous
#include <cuda_runtime.h>
#include <cstdint>

#define N_VARS   2048
#define N_LAYERS 8
#define NODES    4096
#define FAN_IN   4
#define BATCH    8192
#define BT       4              // batch elements per CTA (float4 vector)
#define THREADS  1024
#define NODES_PER_THREAD (NODES / THREADS)   // 4

// Packed per-layer child indices (values < 4096 fit in uint16).
__device__ ushort4 g_idx16[N_LAYERS * NODES];

__global__ void prep_idx_kernel(const int* __restrict__ child_idx) {
    int i = blockIdx.x * blockDim.x + threadIdx.x;
    if (i < N_LAYERS * NODES) {
        const int4 p = reinterpret_cast<const int4*>(child_idx)[i];
        ushort4 v;
        v.x = (unsigned short)(p.x & (NODES - 1));
        v.y = (unsigned short)(p.y & (NODES - 1));
        v.z = (unsigned short)(p.z & (NODES - 1));
        v.w = (unsigned short)(p.w & (NODES - 1));
        g_idx16[i] = v;
    }
}

extern __shared__ float4 s_buf[];   // [2 * NODES] float4 = 128 KB

__global__ __launch_bounds__(THREADS, 1)
void spn_kernel(const float* __restrict__ x,
                const unsigned char* __restrict__ marg,
                float* __restrict__ out) {
    float4* buf0 = s_buf;
    float4* buf1 = s_buf + NODES;

    const int tid = threadIdx.x;
    const int b0  = blockIdx.x * BT;

    // -------- Build leaves: buf0[j] = x[:, j], buf0[j+2048] = 1 - x[:, j] --------
    for (int j = tid; j < N_VARS; j += THREADS) {
        const bool m = (marg[j] != 0);
        float4 v;
        v.x = x[(size_t)(b0 + 0) * N_VARS + j];
        v.y = x[(size_t)(b0 + 1) * N_VARS + j];
        v.z = x[(size_t)(b0 + 2) * N_VARS + j];
        v.w = x[(size_t)(b0 + 3) * N_VARS + j];
        float4 w1, w2;
        if (m) {
            w1 = make_float4(1.f, 1.f, 1.f, 1.f);
            w2 = make_float4(1.f, 1.f, 1.f, 1.f);
        } else {
            w1 = v;
            w2 = make_float4(1.f - v.x, 1.f - v.y, 1.f - v.z, 1.f - v.w);
        }
        buf0[j]          = w1;
        buf0[j + N_VARS] = w2;
    }
    __syncthreads();

    float4* cur = buf0;
    float4* nxt = buf1;
    float4  acc = make_float4(0.f, 0.f, 0.f, 0.f);

    #pragma unroll
    for (int l = 0; l < N_LAYERS; l++) {
        const ushort4* __restrict__ idxL = g_idx16 + l * NODES;

        // Prefetch ALL this thread's index vectors for the layer first so the
        // LDG (L2 ~234cyc) latency is paid once, overlapped, before the LDS chain.
        ushort4 c[NODES_PER_THREAD];
        #pragma unroll
        for (int i = 0; i < NODES_PER_THREAD; i++) {
            c[i] = idxL[tid + i * THREADS];
        }

        #pragma unroll
        for (int i = 0; i < NODES_PER_THREAD; i++) {
            const int node = tid + i * THREADS;
            const float4 a = cur[c[i].x];
            const float4 b = cur[c[i].y];
            const float4 d = cur[c[i].z];
            const float4 e = cur[c[i].w];
            float4 r;
            if ((l & 1) == 0) {   // product layer
                r.x = a.x * b.x * d.x * e.x;
                r.y = a.y * b.y * d.y * e.y;
                r.z = a.z * b.z * d.z * e.z;
                r.w = a.w * b.w * d.w * e.w;
            } else {              // sum layer
                r.x = a.x + b.x + d.x + e.x;
                r.y = a.y + b.y + d.y + e.y;
                r.z = a.z + b.z + d.z + e.z;
                r.w = a.w + b.w + d.w + e.w;
            }
            if (l == N_LAYERS - 1) {
                // Fuse final node-sum: layer 7 is a sum layer, never stored.
                acc.x += r.x; acc.y += r.y; acc.z += r.z; acc.w += r.w;
            } else {
                nxt[node] = r;
            }
        }
        if (l < N_LAYERS - 1) {
            __syncthreads();
        }
        float4* t = cur; cur = nxt; nxt = t;
    }

    // -------- Block reduction of acc (float4) over 1024 threads --------
    #pragma unroll
    for (int off = 16; off > 0; off >>= 1) {
        acc.x += __shfl_down_sync(0xffffffffu, acc.x, off);
        acc.y += __shfl_down_sync(0xffffffffu, acc.y, off);
        acc.z += __shfl_down_sync(0xffffffffu, acc.z, off);
        acc.w += __shfl_down_sync(0xffffffffu, acc.w, off);
    }

    __shared__ float4 warp_sums[THREADS / 32];
    const int wid  = tid >> 5;
    const int lane = tid & 31;
    if (lane == 0) warp_sums[wid] = acc;
    __syncthreads();

    if (wid == 0) {
        float4 s = (lane < THREADS / 32) ? warp_sums[lane]
                                         : make_float4(0.f, 0.f, 0.f, 0.f);
        #pragma unroll
        for (int off = 16; off > 0; off >>= 1) {
            s.x += __shfl_down_sync(0xffffffffu, s.x, off);
            s.y += __shfl_down_sync(0xffffffffu, s.y, off);
            s.z += __shfl_down_sync(0xffffffffu, s.z, off);
            s.w += __shfl_down_sync(0xffffffffu, s.w, off);
        }
        if (lane == 0) {
            *reinterpret_cast<float4*>(out + b0) = s;
        }
    }
}

extern "C" void kernel_launch(void* const* d_in, const int* in_sizes, int n_in,
                              void* d_out, int out_size) {
    const float*         x    = (const float*)d_in[0];
    const unsigned char* marg = (const unsigned char*)d_in[1];
    const int*           cidx = (const int*)d_in[2];   // int64 in reference -> int32 in harness
    float*               out  = (float*)d_out;

    // Allow 128 KB dynamic shared memory (idempotent; not a stream op).
    cudaFuncSetAttribute(spn_kernel,
                         cudaFuncAttributeMaxDynamicSharedMemorySize,
                         2 * NODES * (int)sizeof(float4));

    // 1) Pack int32 indices -> ushort4 (deterministic, re-run every launch).
    {
        const int total = N_LAYERS * NODES;
        const int tpb = 256;
        prep_idx_kernel<<<(total + tpb - 1) / tpb, tpb>>>(cidx);
    }

    // 2) Main fused kernel: one CTA per 4 batch rows.
    spn_kernel<<<BATCH / BT, THREADS, 2 * NODES * (int)sizeof(float4)>>>(x, marg, out);
}

// round 7
// speedup vs baseline: 1.2052x; 1.1990x over previous
#include <cuda_runtime.h>
#include <cstdint>

#define N_VARS   2048
#define N_LAYERS 8
#define NODES    4096
#define FAN_IN   4
#define BATCH    8192
#define BT       4              // batch elements per CTA (float4 vector)
#define THREADS  1024
#define NODES_PER_THREAD (NODES / THREADS)   // 4

// Packed per-layer child indices (values < 4096 fit in uint16).
__device__ ushort4 g_idx16[N_LAYERS * NODES];

__global__ void prep_idx_kernel(const int* __restrict__ child_idx) {
    int i = blockIdx.x * blockDim.x + threadIdx.x;
    if (i < N_LAYERS * NODES) {
        const int4 p = reinterpret_cast<const int4*>(child_idx)[i];
        ushort4 v;
        v.x = (unsigned short)(p.x & (NODES - 1));
        v.y = (unsigned short)(p.y & (NODES - 1));
        v.z = (unsigned short)(p.z & (NODES - 1));
        v.w = (unsigned short)(p.w & (NODES - 1));
        g_idx16[i] = v;
    }
}

// All 24 permutations of 4 elements.
__device__ const unsigned char PERM24[24][4] = {
    {0,1,2,3},{0,1,3,2},{0,2,1,3},{0,2,3,1},{0,3,1,2},{0,3,2,1},
    {1,0,2,3},{1,0,3,2},{1,2,0,3},{1,2,3,0},{1,3,0,2},{1,3,2,0},
    {2,0,1,3},{2,0,3,1},{2,1,0,3},{2,1,3,0},{2,3,0,1},{2,3,1,0},
    {3,0,1,2},{3,0,2,1},{3,1,0,2},{3,1,2,0},{3,2,0,1},{3,2,1,0}
};

// Bank-conflict scheduler: prod/sum are commutative, so the order of the 4
// child gathers is free. LDS.128 conflicts happen within an 8-lane phase
// (8 consecutive nodes) per instruction (slot), keyed by bank-group c & 7.
// Greedily permute each node's children across the 4 slots to spread each
// slot's 8 lanes over the 8 bank-groups. One thread owns one 8-node group.
__global__ void conflict_opt_kernel() {
    int g = blockIdx.x * blockDim.x + threadIdx.x;
    if (g >= N_LAYERS * NODES / 8) return;
    ushort4* base = g_idx16 + (size_t)g * 8;

    unsigned char hist[4][8];
    #pragma unroll
    for (int s = 0; s < 4; s++)
        #pragma unroll
        for (int b = 0; b < 8; b++) hist[s][b] = 0;

    for (int n = 0; n < 8; n++) {
        ushort4 v = base[n];
        unsigned short c[4] = {v.x, v.y, v.z, v.w};
        int best = 0;
        int bestCost = 0x7fffffff;
        for (int p = 0; p < 24; p++) {
            int cost = 0;
            #pragma unroll
            for (int s = 0; s < 4; s++) {
                int h = hist[s][c[PERM24[p][s]] & 7];
                cost += 1 << (2 * h);   // exponential pileup penalty ~ minimizes max multiplicity
            }
            if (cost < bestCost) { bestCost = cost; best = p; }
        }
        ushort4 w;
        w.x = c[PERM24[best][0]];
        w.y = c[PERM24[best][1]];
        w.z = c[PERM24[best][2]];
        w.w = c[PERM24[best][3]];
        #pragma unroll
        for (int s = 0; s < 4; s++) {
            unsigned short cc = c[PERM24[best][s]];
            hist[s][cc & 7]++;
        }
        base[n] = w;
    }
}

extern __shared__ float4 s_buf[];   // [2 * NODES] float4 = 128 KB

__global__ __launch_bounds__(THREADS, 1)
void spn_kernel(const float* __restrict__ x,
                const unsigned char* __restrict__ marg,
                float* __restrict__ out) {
    float4* buf0 = s_buf;
    float4* buf1 = s_buf + NODES;

    const int tid = threadIdx.x;
    const int b0  = blockIdx.x * BT;

    // -------- Build leaves: buf0[j] = x[:, j], buf0[j+2048] = 1 - x[:, j] --------
    for (int j = tid; j < N_VARS; j += THREADS) {
        const bool m = (marg[j] != 0);
        float4 v;
        v.x = x[(size_t)(b0 + 0) * N_VARS + j];
        v.y = x[(size_t)(b0 + 1) * N_VARS + j];
        v.z = x[(size_t)(b0 + 2) * N_VARS + j];
        v.w = x[(size_t)(b0 + 3) * N_VARS + j];
        float4 w1, w2;
        if (m) {
            w1 = make_float4(1.f, 1.f, 1.f, 1.f);
            w2 = make_float4(1.f, 1.f, 1.f, 1.f);
        } else {
            w1 = v;
            w2 = make_float4(1.f - v.x, 1.f - v.y, 1.f - v.z, 1.f - v.w);
        }
        buf0[j]          = w1;
        buf0[j + N_VARS] = w2;
    }
    __syncthreads();

    float4* cur = buf0;
    float4* nxt = buf1;
    float4  acc = make_float4(0.f, 0.f, 0.f, 0.f);

    #pragma unroll
    for (int l = 0; l < N_LAYERS; l++) {
        const ushort4* __restrict__ idxL = g_idx16 + l * NODES;

        // Prefetch this thread's index vectors (L2 latency overlapped).
        ushort4 c[NODES_PER_THREAD];
        #pragma unroll
        for (int i = 0; i < NODES_PER_THREAD; i++) {
            c[i] = idxL[tid + i * THREADS];
        }

        #pragma unroll
        for (int i = 0; i < NODES_PER_THREAD; i++) {
            const int node = tid + i * THREADS;
            const float4 a = cur[c[i].x];
            const float4 b = cur[c[i].y];
            const float4 d = cur[c[i].z];
            const float4 e = cur[c[i].w];
            float4 r;
            if ((l & 1) == 0) {   // product layer
                r.x = a.x * b.x * d.x * e.x;
                r.y = a.y * b.y * d.y * e.y;
                r.z = a.z * b.z * d.z * e.z;
                r.w = a.w * b.w * d.w * e.w;
            } else {              // sum layer
                r.x = a.x + b.x + d.x + e.x;
                r.y = a.y + b.y + d.y + e.y;
                r.z = a.z + b.z + d.z + e.z;
                r.w = a.w + b.w + d.w + e.w;
            }
            if (l == N_LAYERS - 1) {
                // Fuse final node-sum: layer 7 is a sum layer, never stored.
                acc.x += r.x; acc.y += r.y; acc.z += r.z; acc.w += r.w;
            } else {
                nxt[node] = r;
            }
        }
        if (l < N_LAYERS - 1) {
            __syncthreads();
        }
        float4* t = cur; cur = nxt; nxt = t;
    }

    // -------- Block reduction of acc (float4) over 1024 threads --------
    #pragma unroll
    for (int off = 16; off > 0; off >>= 1) {
        acc.x += __shfl_down_sync(0xffffffffu, acc.x, off);
        acc.y += __shfl_down_sync(0xffffffffu, acc.y, off);
        acc.z += __shfl_down_sync(0xffffffffu, acc.z, off);
        acc.w += __shfl_down_sync(0xffffffffu, acc.w, off);
    }

    __shared__ float4 warp_sums[THREADS / 32];
    const int wid  = tid >> 5;
    const int lane = tid & 31;
    if (lane == 0) warp_sums[wid] = acc;
    __syncthreads();

    if (wid == 0) {
        float4 s = (lane < THREADS / 32) ? warp_sums[lane]
                                         : make_float4(0.f, 0.f, 0.f, 0.f);
        #pragma unroll
        for (int off = 16; off > 0; off >>= 1) {
            s.x += __shfl_down_sync(0xffffffffu, s.x, off);
            s.y += __shfl_down_sync(0xffffffffu, s.y, off);
            s.z += __shfl_down_sync(0xffffffffu, s.z, off);
            s.w += __shfl_down_sync(0xffffffffu, s.w, off);
        }
        if (lane == 0) {
            *reinterpret_cast<float4*>(out + b0) = s;
        }
    }
}

extern "C" void kernel_launch(void* const* d_in, const int* in_sizes, int n_in,
                              void* d_out, int out_size) {
    const float*         x    = (const float*)d_in[0];
    const unsigned char* marg = (const unsigned char*)d_in[1];
    const int*           cidx = (const int*)d_in[2];   // int64 in reference -> int32 in harness
    float*               out  = (float*)d_out;

    // Allow 128 KB dynamic shared memory (idempotent; not a stream op).
    cudaFuncSetAttribute(spn_kernel,
                         cudaFuncAttributeMaxDynamicSharedMemorySize,
                         2 * NODES * (int)sizeof(float4));

    // 1) Pack int32 indices -> ushort4 (deterministic, re-run every launch).
    {
        const int total = N_LAYERS * NODES;
        const int tpb = 256;
        prep_idx_kernel<<<(total + tpb - 1) / tpb, tpb>>>(cidx);
    }

    // 2) Bank-conflict scheduling: permute gather slots per 8-node phase group.
    {
        const int groups = N_LAYERS * NODES / 8;   // 4096
        const int tpb = 256;
        conflict_opt_kernel<<<(groups + tpb - 1) / tpb, tpb>>>();
    }

    // 3) Main fused kernel: one CTA per 4 batch rows.
    spn_kernel<<<BATCH / BT, THREADS, 2 * NODES * (int)sizeof(float4)>>>(x, marg, out);
}